// round 1
// baseline (speedup 1.0000x reference)
#include <cuda_runtime.h>
#include <cstdint>

#define BATCH 4
#define NPTS  8192          // N == M == 8192
#define TILE  2048          // refs per shared tile
#define TILE_PAIRS (TILE/2)
#define THREADS 128
#define QPT 2               // queries per thread

// Packed reference layout: per PAIR of points (32 bytes):
//   float4 A = (x0, x1, y0, y1)   float4 B = (z0, z1, s0, s1)  where s = ||p||^2
// One float4 per point => float4 index == point index.
__device__ float4 g_packA[BATCH * NPTS];
__device__ float4 g_packB[BATCH * NPTS];
__device__ float  g_acc;

typedef unsigned long long ull;

__device__ __forceinline__ ull fma2(ull a, ull b, ull c) {
    ull d;
    asm("fma.rn.f32x2 %0, %1, %2, %3;" : "=l"(d) : "l"(a), "l"(b), "l"(c));
    return d;
}
__device__ __forceinline__ ull pack2(float x, float y) {
    ull r;
    asm("mov.b64 %0, {%1, %2};" : "=l"(r) : "f"(x), "f"(y));
    return r;
}
__device__ __forceinline__ void unpack2(ull v, float& lo, float& hi) {
    asm("mov.b64 {%0, %1}, %2;" : "=f"(lo), "=f"(hi) : "l"(v));
}

// Pack both point clouds into pair-interleaved (x,x,y,y,z,z,s,s) layout.
// Also resets the global accumulator (runs before the main kernel each replay).
__global__ void pack_kernel(const float* __restrict__ a, const float* __restrict__ b) {
    int i = blockIdx.x * blockDim.x + threadIdx.x;
    if (i == 0) g_acc = 0.0f;
    if (i >= BATCH * NPTS) return;
    int pair = i >> 1, h = i & 1;
    {
        float x = a[i*3+0], y = a[i*3+1], z = a[i*3+2];
        float s = x*x + y*y + z*z;
        float* o = (float*)g_packA + (size_t)pair * 8;
        o[0+h] = x; o[2+h] = y; o[4+h] = z; o[6+h] = s;
    }
    {
        float x = b[i*3+0], y = b[i*3+1], z = b[i*3+2];
        float s = x*x + y*y + z*z;
        float* o = (float*)g_packB + (size_t)pair * 8;
        o[0+h] = x; o[2+h] = y; o[4+h] = z; o[6+h] = s;
    }
}

__global__ __launch_bounds__(THREADS)
void chamfer_kernel(const float* __restrict__ a, const float* __restrict__ b) {
    __shared__ float4 sh[TILE];          // 32 KB ref tile
    __shared__ float  red[THREADS];

    const int dir   = blockIdx.z;
    const int batch = blockIdx.y;
    const float*  query = (dir == 0) ? a : b;
    const float4* ref   = (dir == 0) ? g_packB : g_packA;

    const int qbase = blockIdx.x * (THREADS * QPT) + threadIdx.x;

    ull   cqx[QPT], cqy[QPT], cqz[QPT];
    float qn[QPT], mlo[QPT], mhi[QPT];

    #pragma unroll
    for (int q = 0; q < QPT; q++) {
        int qi = qbase + q * THREADS;
        const float* qp = query + ((size_t)batch * NPTS + qi) * 3;
        float x = qp[0], y = qp[1], z = qp[2];
        qn[q]  = x*x + y*y + z*z;
        cqx[q] = pack2(-2.0f * x, -2.0f * x);
        cqy[q] = pack2(-2.0f * y, -2.0f * y);
        cqz[q] = pack2(-2.0f * z, -2.0f * z);
        mlo[q] = 3.4e38f; mhi[q] = 3.4e38f;
    }

    const float4* refBase = ref + (size_t)batch * NPTS;   // one float4 per ref point

    for (int t = 0; t < NPTS; t += TILE) {
        __syncthreads();
        const float4* src = refBase + t;
        #pragma unroll
        for (int i = threadIdx.x; i < TILE; i += THREADS) sh[i] = src[i];
        __syncthreads();

        const ulonglong2* shU = (const ulonglong2*)sh;
        #pragma unroll 4
        for (int p = 0; p < TILE_PAIRS; p++) {
            ulonglong2 u0 = shU[2*p + 0];   // (x0,x1),(y0,y1)
            ulonglong2 u1 = shU[2*p + 1];   // (z0,z1),(s0,s1)
            #pragma unroll
            for (int q = 0; q < QPT; q++) {
                ull d = fma2(cqx[q], u0.x, u1.y);   // -2ax*bx + ||b||^2
                d = fma2(cqy[q], u0.y, d);
                d = fma2(cqz[q], u1.x, d);
                float dl, dh; unpack2(d, dl, dh);
                mlo[q] = fminf(mlo[q], dl);
                mhi[q] = fminf(mhi[q], dh);
            }
        }
    }

    float tsum = 0.0f;
    #pragma unroll
    for (int q = 0; q < QPT; q++)
        tsum += fminf(mlo[q], mhi[q]) + qn[q];   // shift back by ||a||^2

    red[threadIdx.x] = tsum;
    __syncthreads();
    #pragma unroll
    for (int s = THREADS / 2; s > 0; s >>= 1) {
        if (threadIdx.x < s) red[threadIdx.x] += red[threadIdx.x + s];
        __syncthreads();
    }
    if (threadIdx.x == 0) atomicAdd(&g_acc, red[0]);
}

__global__ void finalize_kernel(float* __restrict__ out) {
    out[0] = g_acc * (1.0f / (float)(BATCH * NPTS));
}

extern "C" void kernel_launch(void* const* d_in, const int* in_sizes, int n_in,
                              void* d_out, int out_size) {
    const float* a = (const float*)d_in[0];
    const float* b = (const float*)d_in[1];

    pack_kernel<<<(BATCH * NPTS + 255) / 256, 256>>>(a, b);

    dim3 grid(NPTS / (THREADS * QPT), BATCH, 2);   // (32, 4, 2) = 256 CTAs
    chamfer_kernel<<<grid, THREADS>>>(a, b);

    finalize_kernel<<<1, 1>>>((float*)d_out);
}

// round 2
// speedup vs baseline: 1.2227x; 1.2227x over previous
#include <cuda_runtime.h>
#include <cstdint>

#define BATCH 4
#define NPTS  8192
#define THREADS 128
#define QPT 4
#define QTILE (THREADS * QPT)        // 512 queries per CTA
#define NQT   (NPTS / QTILE)         // 16 query tiles per (batch,dir)
#define RCHUNK 1024                  // refs per CTA
#define RPAIRS (RCHUNK / 2)
#define RSPLIT (NPTS / RCHUNK)       // 8 ref chunks
#define NQ_ALL (2 * BATCH * NPTS)    // 65536 total queries

// Per-(chunk, query) partial minima. Written by stage 1, combined by reduce.
__device__ float g_part[RSPLIT][NQ_ALL];   // 2 MB
__device__ float g_bsum[64];

typedef unsigned long long ull;

__device__ __forceinline__ ull fma2(ull a, ull b, ull c) {
    ull d;
    asm("fma.rn.f32x2 %0, %1, %2, %3;" : "=l"(d) : "l"(a), "l"(b), "l"(c));
    return d;
}
__device__ __forceinline__ ull pack2(float x, float y) {
    ull r;
    asm("mov.b64 %0, {%1, %2};" : "=l"(r) : "f"(x), "f"(y));
    return r;
}
__device__ __forceinline__ void unpack2(ull v, float& lo, float& hi) {
    asm("mov.b64 {%0, %1}, %2;" : "=f"(lo), "=f"(hi) : "l"(v));
}

// Stage 1: each CTA handles 512 queries x 1024 refs for one (batch, dir).
// Ref chunk is packed inline into shared as pair-interleaved
// (x0,x1,y0,y1)(z0,z1,s0,s1) float4 pairs, s = ||p||^2.
__global__ __launch_bounds__(THREADS)
void chamfer_kernel(const float* __restrict__ a, const float* __restrict__ b) {
    __shared__ float4 sh[RCHUNK];    // 16 KB

    const int dir   = blockIdx.z;
    const int batch = blockIdx.y;
    const int rs    = blockIdx.x / NQT;
    const int qt    = blockIdx.x % NQT;

    const float* query = dir ? b : a;
    const float* ref   = dir ? a : b;

    // ---- pack ref chunk into shared ----
    const float* rbase = ref + ((size_t)batch * NPTS + (size_t)rs * RCHUNK) * 3;
    #pragma unroll
    for (int p = threadIdx.x; p < RCHUNK; p += THREADS) {
        float x = rbase[p * 3 + 0];
        float y = rbase[p * 3 + 1];
        float z = rbase[p * 3 + 2];
        float s = x * x + y * y + z * z;
        float* o = (float*)sh + (size_t)(p >> 1) * 8;
        int h = p & 1;
        o[0 + h] = x; o[2 + h] = y; o[4 + h] = z; o[6 + h] = s;
    }

    // ---- load queries ----
    const int qbase = qt * QTILE + threadIdx.x;
    ull   cqx[QPT], cqy[QPT], cqz[QPT];
    float qn[QPT], mlo[QPT], mhi[QPT];

    #pragma unroll
    for (int q = 0; q < QPT; q++) {
        int qi = qbase + q * THREADS;
        const float* qp = query + ((size_t)batch * NPTS + qi) * 3;
        float x = qp[0], y = qp[1], z = qp[2];
        qn[q]  = x * x + y * y + z * z;
        cqx[q] = pack2(-2.0f * x, -2.0f * x);
        cqy[q] = pack2(-2.0f * y, -2.0f * y);
        cqz[q] = pack2(-2.0f * z, -2.0f * z);
        mlo[q] = 3.4e38f; mhi[q] = 3.4e38f;
    }

    __syncthreads();

    // ---- main loop: d = ||b||^2 - 2 a.b  (shift-invariant for min) ----
    const ulonglong2* shU = (const ulonglong2*)sh;
    #pragma unroll 4
    for (int p = 0; p < RPAIRS; p++) {
        ulonglong2 u0 = shU[2 * p + 0];   // (x0,x1),(y0,y1)
        ulonglong2 u1 = shU[2 * p + 1];   // (z0,z1),(s0,s1)
        #pragma unroll
        for (int q = 0; q < QPT; q++) {
            ull d = fma2(cqx[q], u0.x, u1.y);
            d = fma2(cqy[q], u0.y, d);
            d = fma2(cqz[q], u1.x, d);
            float dl, dh; unpack2(d, dl, dh);
            mlo[q] = fminf(mlo[q], dl);
            mhi[q] = fminf(mhi[q], dh);
        }
    }

    // ---- write per-query partial minima (shifted back by ||a||^2) ----
    const int flat = (dir * BATCH + batch) * NPTS;
    #pragma unroll
    for (int q = 0; q < QPT; q++) {
        int qi = qbase + q * THREADS;
        g_part[rs][flat + qi] = fminf(mlo[q], mhi[q]) + qn[q];
    }
}

// Stage 2: min across ref chunks, sum within block. 64 CTAs x 1024 threads.
__global__ __launch_bounds__(1024)
void reduce_kernel() {
    __shared__ float red[1024];
    int q = blockIdx.x * 1024 + threadIdx.x;
    float m = g_part[0][q];
    #pragma unroll
    for (int rs = 1; rs < RSPLIT; rs++) m = fminf(m, g_part[rs][q]);
    red[threadIdx.x] = m;
    __syncthreads();
    #pragma unroll
    for (int s = 512; s > 0; s >>= 1) {
        if (threadIdx.x < s) red[threadIdx.x] += red[threadIdx.x + s];
        __syncthreads();
    }
    if (threadIdx.x == 0) g_bsum[blockIdx.x] = red[0];
}

__global__ void finalize_kernel(float* __restrict__ out) {
    __shared__ float red[64];
    red[threadIdx.x] = g_bsum[threadIdx.x];
    __syncthreads();
    #pragma unroll
    for (int s = 32; s > 0; s >>= 1) {
        if (threadIdx.x < s) red[threadIdx.x] += red[threadIdx.x + s];
        __syncthreads();
    }
    if (threadIdx.x == 0) out[0] = red[0] * (1.0f / (float)(BATCH * NPTS));
}

extern "C" void kernel_launch(void* const* d_in, const int* in_sizes, int n_in,
                              void* d_out, int out_size) {
    const float* a = (const float*)d_in[0];
    const float* b = (const float*)d_in[1];

    dim3 grid(NQT * RSPLIT, BATCH, 2);   // (128, 4, 2) = 1024 CTAs
    chamfer_kernel<<<grid, THREADS>>>(a, b);
    reduce_kernel<<<64, 1024>>>();
    finalize_kernel<<<1, 64>>>((float*)d_out);
}

// round 3
// speedup vs baseline: 1.2975x; 1.0611x over previous
#include <cuda_runtime.h>
#include <cstdint>

#define BATCH 4
#define NPTS  8192
#define THREADS 128
#define QPT 8
#define QTILE (THREADS * QPT)        // 1024 queries per CTA
#define NQT   (NPTS / QTILE)         // 8 query tiles per (batch,dir)
#define RCHUNK 256                   // refs per CTA
#define RPAIRS (RCHUNK / 2)          // 128
#define RSPLIT (NPTS / RCHUNK)       // 32 ref chunks
#define NQ_ALL (2 * BATCH * NPTS)    // 65536 total queries

// Per-(chunk, query) partial minima, WITHOUT the ||q||^2 shift (added in stage 2).
__device__ float g_part[RSPLIT][NQ_ALL];   // 8 MB
__device__ float g_bsum[64];

typedef unsigned long long ull;

__device__ __forceinline__ ull fma2(ull a, ull b, ull c) {
    ull d;
    asm("fma.rn.f32x2 %0, %1, %2, %3;" : "=l"(d) : "l"(a), "l"(b), "l"(c));
    return d;
}
__device__ __forceinline__ ull pack2(float x, float y) {
    ull r;
    asm("mov.b64 %0, {%1, %2};" : "=l"(r) : "f"(x), "f"(y));
    return r;
}
__device__ __forceinline__ void unpack2(ull v, float& lo, float& hi) {
    asm("mov.b64 {%0, %1}, %2;" : "=f"(lo), "=f"(hi) : "l"(v));
}

// Stage 1: each CTA = 1024 queries x 256 refs for one (batch, dir).
// Refs packed inline into shared as pair-interleaved float4 pairs:
// (x0,x1,y0,y1)(z0,z1,s0,s1), s = ||p||^2.
__global__ __launch_bounds__(THREADS, 5)
void chamfer_kernel(const float* __restrict__ a, const float* __restrict__ b) {
    __shared__ float4 sh[RCHUNK];    // 4 KB

    const int dir   = blockIdx.z;
    const int batch = blockIdx.y;
    const int rs    = blockIdx.x / NQT;
    const int qt    = blockIdx.x % NQT;

    const float* query = dir ? b : a;
    const float* ref   = dir ? a : b;

    // ---- pack ref chunk into shared ----
    const float* rbase = ref + ((size_t)batch * NPTS + (size_t)rs * RCHUNK) * 3;
    #pragma unroll
    for (int p = threadIdx.x; p < RCHUNK; p += THREADS) {
        float x = rbase[p * 3 + 0];
        float y = rbase[p * 3 + 1];
        float z = rbase[p * 3 + 2];
        float s = x * x + y * y + z * z;
        float* o = (float*)sh + (size_t)(p >> 1) * 8;
        int h = p & 1;
        o[0 + h] = x; o[2 + h] = y; o[4 + h] = z; o[6 + h] = s;
    }

    // ---- load queries (no qn here; added in stage 2) ----
    const int qbase = qt * QTILE + threadIdx.x;
    ull   cqx[QPT], cqy[QPT], cqz[QPT];
    float mlo[QPT], mhi[QPT];

    #pragma unroll
    for (int q = 0; q < QPT; q++) {
        int qi = qbase + q * THREADS;
        const float* qp = query + ((size_t)batch * NPTS + qi) * 3;
        float x = qp[0], y = qp[1], z = qp[2];
        cqx[q] = pack2(-2.0f * x, -2.0f * x);
        cqy[q] = pack2(-2.0f * y, -2.0f * y);
        cqz[q] = pack2(-2.0f * z, -2.0f * z);
        mlo[q] = 3.4e38f; mhi[q] = 3.4e38f;
    }

    __syncthreads();

    // ---- main loop: d = ||b||^2 - 2 q.b  (shift-invariant for min) ----
    const ulonglong2* shU = (const ulonglong2*)sh;
    #pragma unroll 4
    for (int p = 0; p < RPAIRS; p++) {
        ulonglong2 u0 = shU[2 * p + 0];   // (x0,x1),(y0,y1)
        ulonglong2 u1 = shU[2 * p + 1];   // (z0,z1),(s0,s1)
        #pragma unroll
        for (int q = 0; q < QPT; q++) {
            ull d = fma2(cqx[q], u0.x, u1.y);
            d = fma2(cqy[q], u0.y, d);
            d = fma2(cqz[q], u1.x, d);
            float dl, dh; unpack2(d, dl, dh);
            mlo[q] = fminf(mlo[q], dl);
            mhi[q] = fminf(mhi[q], dh);
        }
    }

    // ---- write per-query partial minima ----
    const int flat = (dir * BATCH + batch) * NPTS;
    #pragma unroll
    for (int q = 0; q < QPT; q++) {
        int qi = qbase + q * THREADS;
        g_part[rs][flat + qi] = fminf(mlo[q], mhi[q]);
    }
}

// Stage 2: min across ref chunks, add ||q||^2, sum within block.
// 64 CTAs x 1024 threads, 1 query per thread.
__global__ __launch_bounds__(1024)
void reduce_kernel(const float* __restrict__ a, const float* __restrict__ b) {
    __shared__ float red[1024];
    int q = blockIdx.x * 1024 + threadIdx.x;

    float m = g_part[0][q];
    #pragma unroll
    for (int rs = 1; rs < RSPLIT; rs++) m = fminf(m, g_part[rs][q]);

    // recompute ||q||^2
    int dir = q >> 15;                 // q / 32768
    int loc = q & 32767;               // (batch*NPTS + qi)
    const float* qp = (dir ? b : a) + (size_t)loc * 3;
    float x = qp[0], y = qp[1], z = qp[2];
    m += x * x + y * y + z * z;

    red[threadIdx.x] = m;
    __syncthreads();
    #pragma unroll
    for (int s = 512; s > 0; s >>= 1) {
        if (threadIdx.x < s) red[threadIdx.x] += red[threadIdx.x + s];
        __syncthreads();
    }
    if (threadIdx.x == 0) g_bsum[blockIdx.x] = red[0];
}

__global__ void finalize_kernel(float* __restrict__ out) {
    __shared__ float red[64];
    red[threadIdx.x] = g_bsum[threadIdx.x];
    __syncthreads();
    #pragma unroll
    for (int s = 32; s > 0; s >>= 1) {
        if (threadIdx.x < s) red[threadIdx.x] += red[threadIdx.x + s];
        __syncthreads();
    }
    if (threadIdx.x == 0) out[0] = red[0] * (1.0f / (float)(BATCH * NPTS));
}

extern "C" void kernel_launch(void* const* d_in, const int* in_sizes, int n_in,
                              void* d_out, int out_size) {
    const float* a = (const float*)d_in[0];
    const float* b = (const float*)d_in[1];

    dim3 grid(NQT * RSPLIT, BATCH, 2);   // (256, 4, 2) = 2048 CTAs
    chamfer_kernel<<<grid, THREADS>>>(a, b);
    reduce_kernel<<<64, 1024>>>(a, b);
    finalize_kernel<<<1, 64>>>((float*)d_out);
}